// round 13
// baseline (speedup 1.0000x reference)
#include <cuda_runtime.h>
#include <math.h>
#include <stdint.h>

#define IMG    64
#define NSLICE 16
#define NCOIL  4
#define NSING  4
#define NECHO  3
#define NRO    32
#define NPT    96
#define NEC    (NECHO * NCOIL)   // 12
#define NPIX   (IMG * IMG)       // 4096

// scf[kz][c][ne=n*3+e][pix]  (25 MB)   pixel index = X*64+Y (X major)
__device__ float2 g_scf[NSLICE * NCOIL * (NSING * NECHO) * NPIX];
// transposed singulars: tsing[ne][z][pix]  (6.3 MB)
__device__ float2 g_tsing[(NSING * NECHO) * NSLICE * NPIX];
// phase tables
__device__ float2 g_exT[NRO * NPT * IMG];    // exT[r][p][x] = exp(-i*w0*(x-32))
__device__ float2 g_ey_[NRO * IMG * NPT];    // ey[r][y][p]  = exp(-i*w1*(y-32))

// ---------------------------------------------------------------------------
// helpers
// ---------------------------------------------------------------------------
__device__ __forceinline__ float tf32r(float f) {
    uint32_t u;
    asm("cvt.rn.tf32.f32 %0, %1;" : "=r"(u) : "f"(f));
    return __uint_as_float(u);
}
__device__ __forceinline__ void mma_tf32(float* d, const uint32_t* a, const uint32_t* b) {
    asm volatile(
        "mma.sync.aligned.m16n8k8.row.col.f32.tf32.tf32.f32 "
        "{%0,%1,%2,%3}, {%4,%5,%6,%7}, {%8,%9}, {%0,%1,%2,%3};"
        : "+f"(d[0]), "+f"(d[1]), "+f"(d[2]), "+f"(d[3])
        : "r"(a[0]), "r"(a[1]), "r"(a[2]), "r"(a[3]), "r"(b[0]), "r"(b[1]));
}

// ---------------------------------------------------------------------------
// Transpose: singulars [pix][z][ne]{2} -> g_tsing [ne][z][pix]{2}
// ---------------------------------------------------------------------------
__global__ __launch_bounds__(256)
void transpose_kernel(const float* __restrict__ singulars)   // [64,64,16,4,3,2]
{
    __shared__ float sS[256][25];   // 24 floats + pad
    const int z  = blockIdx.y;
    const int pb = blockIdx.x * 256;
    const int t  = threadIdx.x;

    const float4* src = (const float4*)(singulars + (size_t)(pb + t) * 384 + z * 24);
#pragma unroll
    for (int q = 0; q < 6; ++q) {
        float4 f = src[q];
        sS[t][4 * q + 0] = f.x; sS[t][4 * q + 1] = f.y;
        sS[t][4 * q + 2] = f.z; sS[t][4 * q + 3] = f.w;
    }
    __syncthreads();

#pragma unroll
    for (int j = 0; j < 12; ++j) {
        g_tsing[((size_t)j * NSLICE + z) * NPIX + pb + t]
            = make_float2(sS[t][2 * j], sS[t][2 * j + 1]);
    }
}

// ---------------------------------------------------------------------------
// Stage A (radix-2 DIF over z), same as round 12.
// ---------------------------------------------------------------------------
__global__ __launch_bounds__(256, 3)
void stageA_kernel(const float* __restrict__ smap)   // [4,64,64,16,2]
{
    __shared__ float2 T8[8][8];     // w8^(m z0)
    __shared__ float2 T8s[8][8];    // sign(z0) * w8^(m z0)
    __shared__ float2 tws[8];       // sign(z0) * w16^(z0)
    __shared__ float2 sSm[256][17]; // staged smap tile, padded

    const int pixb = blockIdx.x * 256;
    const int t    = threadIdx.x;
    const int pix  = pixb + t;
    const int j    = blockIdx.y;
    const int c    = j & 3;
    const int ne   = j >> 2;               // n*3+e

    if (t < 64) {
        int z0 = t >> 3, m = t & 7;
        float ang = -(2.0f * (float)M_PI / 8.0f) * (float)(m * z0);
        float s, co; sincosf(ang, &s, &co);
        T8[z0][m] = make_float2(co, s);
        float sgn = (z0 & 1) ? -1.0f : 1.0f;
        T8s[z0][m] = make_float2(co * sgn, s * sgn);
    }
    if (t < 8) {
        float ang = -(2.0f * (float)M_PI / 16.0f) * (float)t;
        float s, co; sincosf(ang, &s, &co);
        float sgn = (t & 1) ? -1.0f : 1.0f;
        tws[t] = make_float2(co * sgn, s * sgn);
    }
    {
        const float2* smap2 = (const float2*)(smap) + ((size_t)c * NPIX + pixb) * NSLICE;
        for (int i = t; i < 256 * NSLICE; i += 256)
            sSm[i >> 4][i & 15] = smap2[i];
    }
    __syncthreads();

    const float2* vsrc = g_tsing + (size_t)ne * NSLICE * NPIX + pix;

    float aEr[8], aEi[8], aOr[8], aOi[8];
#pragma unroll
    for (int m = 0; m < 8; ++m) { aEr[m] = 0.f; aEi[m] = 0.f; aOr[m] = 0.f; aOi[m] = 0.f; }

#pragma unroll
    for (int z0 = 0; z0 < 8; ++z0) {
        float2 v0 = vsrc[(size_t)z0 * NPIX];
        float2 v8 = vsrc[(size_t)(z0 + 8) * NPIX];
        float2 s0 = sSm[t][z0];
        float2 s8 = sSm[t][z0 + 8];

        float t0r = v0.x * s0.x - v0.y * s0.y;
        float t0i = v0.x * s0.y + v0.y * s0.x;
        float t8r = v8.x * s8.x - v8.y * s8.y;
        float t8i = v8.x * s8.y + v8.y * s8.x;

        float ar  = t0r + t8r, ai = t0i + t8i;
        float bpr = t0r - t8r, bpi = t0i - t8i;
        float2 tw = tws[z0];
        float br = bpr * tw.x - bpi * tw.y;
        float bi = bpr * tw.y + bpi * tw.x;

#pragma unroll
        for (int m = 0; m < 8; ++m) {
            float2 wE = T8s[z0][m];
            aEr[m] = fmaf(ar, wE.x, aEr[m]);  aEr[m] = fmaf(-ai, wE.y, aEr[m]);
            aEi[m] = fmaf(ar, wE.y, aEi[m]);  aEi[m] = fmaf( ai, wE.x, aEi[m]);
            float2 wO = T8[z0][m];
            aOr[m] = fmaf(br, wO.x, aOr[m]);  aOr[m] = fmaf(-bi, wO.y, aOr[m]);
            aOi[m] = fmaf(br, wO.y, aOi[m]);  aOi[m] = fmaf( bi, wO.x, aOi[m]);
        }
    }

#pragma unroll
    for (int m = 0; m < 8; ++m) {
        g_scf[(((size_t)(2 * m) * NCOIL + c) * 12 + ne) * NPIX + pix]
            = make_float2(aEr[m], aEi[m]);
        g_scf[(((size_t)(2 * m + 1) * NCOIL + c) * 12 + ne) * NPIX + pix]
            = make_float2(aOr[m], aOi[m]);
    }
}

// ---------------------------------------------------------------------------
// Phase tables. grid 32, block 384.  ex stored transposed [p][x].
// ---------------------------------------------------------------------------
__global__ __launch_bounds__(384)
void exgen_kernel(const float* __restrict__ ktraj)   // [1,32,96,2]
{
    const int r = blockIdx.x;
    const int p = threadIdx.x % NPT;
    const int g = threadIdx.x / NPT;       // 0..3, 16 steps each
    const float w0 = ktraj[(r * NPT + p) * 2 + 0];
    const float w1 = ktraj[(r * NPT + p) * 2 + 1];

    {
        float s, c; sincosf(w0, &s, &c);                      // step exp(-i*w0)
        float pr, pi; sincosf(w0 * (32.0f - g * 16.0f), &pi, &pr);
#pragma unroll 4
        for (int jj = 0; jj < 16; ++jj) {
            int x = g * 16 + jj;
            g_exT[((size_t)r * NPT + p) * IMG + x] = make_float2(pr, pi);
            float t = pr;
            pr = fmaf(pr, c, pi * s);
            pi = fmaf(pi, c, -(t * s));
        }
    }
    {
        float s, c; sincosf(w1, &s, &c);
        float pr, pi; sincosf(w1 * (32.0f - g * 16.0f), &pi, &pr);
#pragma unroll 4
        for (int jj = 0; jj < 16; ++jj) {
            int y = g * 16 + jj;
            g_ey_[((size_t)r * IMG + y) * NPT + p] = make_float2(pr, pi);
            float t = pr;
            pr = fmaf(pr, c, pi * s);
            pi = fmaf(pi, c, -(t * s));
        }
    }
}

// ---------------------------------------------------------------------------
// NUFFT via warp-level mma.sync (tf32), k-split across blocks:
//   per (r, ec, kh): partial C[96x128] over y in [32kh, 32kh+32)
//   A = [ey.re | -ey.im] (96 x 64), B rows [x | 64+x] = [re|im ; im|-re]
// Epilogue contracts ex directly from accumulator registers (no C smem),
// shared-atomic partial reduce, global atomicAdd into out.
// grid (32 r, 4 ecg, 2 kh), block 256 (8 warps: m2 x n4, 4 n-tiles each).
// smem ~60KB -> 3 blocks/SM.
// ---------------------------------------------------------------------------
#define KS2      68                   // float stride (== 4 mod 32)
#define A_FL     (96 * KS2)
#define B_FL     (128 * KS2)

__global__ __launch_bounds__(256, 3)
void nufft_mma_kernel(const float* __restrict__ ur_list,   // [1,32,4]
                      const int*   __restrict__ sbin,      // [32]
                      float2* __restrict__ out)            // [96,4,32,3]
{
    extern __shared__ float sh[];
    float*  sA   = sh;                        // [96][KS2]
    float*  sB   = sh + A_FL;                 // [128][KS2]
    float2* sPar = (float2*)(sB + B_FL);      // [96]

    const int r    = blockIdx.x;
    const int ecg  = blockIdx.y;
    const int kh   = blockIdx.z;              // y-half
    const int tid  = threadIdx.x;
    const int lane = tid & 31;
    const int w    = tid >> 5;      // 0..7
    const int g    = lane >> 2;     // 0..7
    const int tg   = lane & 3;      // 0..3
    const int mg   = w >> 2;        // 0..1  (m-rows 48*mg ..)
    const int ng   = w & 3;         // 0..3  (n-cols 32*ng ..)

    // ---- build A (tf32): A[p][yl] = ey.re[y], A[p][32+yl] = -ey.im[y] ----
    {
        const float2* gey = g_ey_ + ((size_t)r * IMG + 32 * kh) * NPT;
        for (int i = tid; i < 96 * 32; i += 256) {
            int p = i % NPT, yl = i / NPT;
            float2 e = gey[yl * NPT + p];
            sA[p * KS2 + yl]      = tf32r(e.x);
            sA[p * KS2 + 32 + yl] = tf32r(-e.y);
        }
    }

    const int kzr = sbin[r];
    const float u0 = ur_list[r * NSING + 0];
    const float u1 = ur_list[r * NSING + 1];
    const float u2 = ur_list[r * NSING + 2];
    const float u3 = ur_list[r * NSING + 3];

    const float*  Abase = sA + (mg * 48 + g) * KS2 + tg;
    const float4* gexT4 = (const float4*)(g_exT + (size_t)r * NPT * IMG);
    // gexT4[(p*IMG + x)/2] covers (x, x+1) float2 pairs

    for (int it = 0; it < 3; ++it) {
        const int ec = ecg * 3 + it;
        const int e  = ec >> 2;
        const int c  = ec & 3;

        __syncthreads();   // prior global-add readers of sPar / A-build done

        // ---- build B for this ec (fused Ur mix), y-half only ----
        const float2* base = g_scf
            + ((size_t)(kzr * NCOIL + c) * 12 + e) * NPIX + 32 * kh;
        for (int jj = 0; jj < 8; ++jj) {
            int q  = tid + jj * 256;          // 0..2047
            int x  = q >> 5, yl = q & 31;
            int ip = x * IMG + yl;            // offset by 32*kh already in base
            float2 s0 = base[ip];
            float2 s1 = base[ip + 3 * NPIX];
            float2 s2 = base[ip + 6 * NPIX];
            float2 s3 = base[ip + 9 * NPIX];
            float ar = fmaf(u0, s0.x, fmaf(u1, s1.x, fmaf(u2, s2.x, u3 * s3.x)));
            float ai = fmaf(u0, s0.y, fmaf(u1, s1.y, fmaf(u2, s2.y, u3 * s3.y)));
            float tar = tf32r(ar), tai = tf32r(ai);
            sB[x * KS2 + yl]             = tar;
            sB[x * KS2 + 32 + yl]        = tai;
            sB[(64 + x) * KS2 + yl]      = tai;
            sB[(64 + x) * KS2 + 32 + yl] = tf32r(-ar);
        }
        if (tid < 96) sPar[tid] = make_float2(0.f, 0.f);
        __syncthreads();

        // ---- mma mainloop: K = 64 in 8 k8 steps ----
        float d[3][4][4];
#pragma unroll
        for (int mt = 0; mt < 3; ++mt)
#pragma unroll
            for (int nt = 0; nt < 4; ++nt)
#pragma unroll
                for (int q = 0; q < 4; ++q) d[mt][nt][q] = 0.f;

#pragma unroll
        for (int k0 = 0; k0 < 64; k0 += 8) {
            uint32_t a[3][4], b[4][2];
#pragma unroll
            for (int mt = 0; mt < 3; ++mt) {
                const float* ap = Abase + mt * 16 * KS2 + k0;
                a[mt][0] = __float_as_uint(ap[0]);
                a[mt][1] = __float_as_uint(ap[8 * KS2]);
                a[mt][2] = __float_as_uint(ap[4]);
                a[mt][3] = __float_as_uint(ap[8 * KS2 + 4]);
            }
#pragma unroll
            for (int nt = 0; nt < 4; ++nt) {
                const float* bp = sB + (ng * 32 + nt * 8 + g) * KS2 + tg + k0;
                b[nt][0] = __float_as_uint(bp[0]);
                b[nt][1] = __float_as_uint(bp[4]);
            }
#pragma unroll
            for (int mt = 0; mt < 3; ++mt)
#pragma unroll
                for (int nt = 0; nt < 4; ++nt)
                    mma_tf32(d[mt][nt], a[mt], b[nt]);
        }

        // ---- register epilogue: contract ex directly from accumulators ----
        // lane value d[mt][nt][q]:  p = mg*48+mt*16+g (+8 for q>=2),
        //                           n = ng*32+nt*8+2tg (+1 for odd q)
        // n<64 -> re(t1) at x=n ; n>=64 -> im(t1) at x=n-64  (uniform per warp)
        const bool isRe = (ng < 2);
#pragma unroll
        for (int mt = 0; mt < 3; ++mt) {
            const int p = mg * 48 + mt * 16 + g;
            float prA = 0.f, piA = 0.f, prB = 0.f, piB = 0.f;
#pragma unroll
            for (int nt = 0; nt < 4; ++nt) {
                const int x = (ng & 1) * 32 + nt * 8 + 2 * tg;   // x for this pair
                float4 fa = gexT4[(p * IMG + x) >> 1];           // ex[x], ex[x+1] @ row p
                float4 fb = gexT4[((p + 8) * IMG + x) >> 1];     // @ row p+8
                if (isRe) {
                    prA = fmaf(d[mt][nt][0], fa.x, prA);  piA = fmaf(d[mt][nt][0], fa.y, piA);
                    prA = fmaf(d[mt][nt][1], fa.z, prA);  piA = fmaf(d[mt][nt][1], fa.w, piA);
                    prB = fmaf(d[mt][nt][2], fb.x, prB);  piB = fmaf(d[mt][nt][2], fb.y, piB);
                    prB = fmaf(d[mt][nt][3], fb.z, prB);  piB = fmaf(d[mt][nt][3], fb.w, piB);
                } else {
                    prA = fmaf(-d[mt][nt][0], fa.y, prA); piA = fmaf(d[mt][nt][0], fa.x, piA);
                    prA = fmaf(-d[mt][nt][1], fa.w, prA); piA = fmaf(d[mt][nt][1], fa.z, piA);
                    prB = fmaf(-d[mt][nt][2], fb.y, prB); piB = fmaf(d[mt][nt][2], fb.x, piB);
                    prB = fmaf(-d[mt][nt][3], fb.w, prB); piB = fmaf(d[mt][nt][3], fb.z, piB);
                }
            }
            atomicAdd(&sPar[p].x, prA);     atomicAdd(&sPar[p].y, piA);
            atomicAdd(&sPar[p + 8].x, prB); atomicAdd(&sPar[p + 8].y, piB);
        }
        __syncthreads();

        if (tid < NPT) {
            float2 v = sPar[tid];
            float* dst = (float*)&out[((tid * NCOIL + c) * NRO + r) * NECHO + e];
            atomicAdd(dst,     v.x);
            atomicAdd(dst + 1, v.y);
        }
    }
}

// ---------------------------------------------------------------------------
extern "C" void kernel_launch(void* const* d_in, const int* in_sizes, int n_in,
                              void* d_out, int out_size)
{
    const float* singulars = (const float*)d_in[0];
    const float* smap      = (const float*)d_in[1];
    const float* ktraj     = (const float*)d_in[2];
    const float* ur_list   = (const float*)d_in[3];
    const int*   sbin      = (const int*)d_in[4];
    // d_in[5] = dc (unused by the forward reference)

    float2* out = (float2*)d_out;

    const int smemNufft = (A_FL + B_FL) * (int)sizeof(float)
                        + 96 * (int)sizeof(float2);       // ~60.3KB
    cudaFuncSetAttribute(nufft_mma_kernel,
                         cudaFuncAttributeMaxDynamicSharedMemorySize, smemNufft);

    cudaMemsetAsync(d_out, 0, (size_t)out_size * sizeof(float));
    transpose_kernel<<<dim3(16, 16), 256>>>(singulars);
    exgen_kernel<<<NRO, 384>>>(ktraj);
    stageA_kernel<<<dim3(16, 48), 256>>>(smap);
    nufft_mma_kernel<<<dim3(NRO, 4, 2), 256, smemNufft>>>(ur_list, sbin, out);
}

// round 14
// speedup vs baseline: 1.1980x; 1.1980x over previous
#include <cuda_runtime.h>
#include <math.h>
#include <stdint.h>

#define IMG    64
#define NSLICE 16
#define NCOIL  4
#define NSING  4
#define NECHO  3
#define NRO    32
#define NPT    96
#define NEC    (NECHO * NCOIL)   // 12
#define NPIX   (IMG * IMG)       // 4096

// scf[kz][c][ne=n*3+e][pix]  (25 MB)   pixel index = X*64+Y (X major)
__device__ float2 g_scf[NSLICE * NCOIL * (NSING * NECHO) * NPIX];
// transposed singulars: tsing[ne][z][pix]  (6.3 MB)
__device__ float2 g_tsing[(NSING * NECHO) * NSLICE * NPIX];
// phase tables
__device__ float2 g_exp_[NRO * IMG * NPT];   // ex[r][x][p] = exp(-i*w0*(x-32))
__device__ float2 g_ey_[NRO * IMG * NPT];    // ey[r][y][p] = exp(-i*w1*(y-32))

// ---------------------------------------------------------------------------
// helpers
// ---------------------------------------------------------------------------
__device__ __forceinline__ float tf32r(float f) {
    uint32_t u;
    asm("cvt.rn.tf32.f32 %0, %1;" : "=r"(u) : "f"(f));
    return __uint_as_float(u);
}
__device__ __forceinline__ void mma_tf32(float* d, const uint32_t* a, const uint32_t* b) {
    asm volatile(
        "mma.sync.aligned.m16n8k8.row.col.f32.tf32.tf32.f32 "
        "{%0,%1,%2,%3}, {%4,%5,%6,%7}, {%8,%9}, {%0,%1,%2,%3};"
        : "+f"(d[0]), "+f"(d[1]), "+f"(d[2]), "+f"(d[3])
        : "r"(a[0]), "r"(a[1]), "r"(a[2]), "r"(a[3]), "r"(b[0]), "r"(b[1]));
}

// ---------------------------------------------------------------------------
// Transpose: singulars [pix][z][ne]{2} -> g_tsing [ne][z][pix]{2}
// ---------------------------------------------------------------------------
__global__ __launch_bounds__(256)
void transpose_kernel(const float* __restrict__ singulars)   // [64,64,16,4,3,2]
{
    __shared__ float sS[256][25];   // 24 floats + pad
    const int z  = blockIdx.y;
    const int pb = blockIdx.x * 256;
    const int t  = threadIdx.x;

    const float4* src = (const float4*)(singulars + (size_t)(pb + t) * 384 + z * 24);
#pragma unroll
    for (int q = 0; q < 6; ++q) {
        float4 f = src[q];
        sS[t][4 * q + 0] = f.x; sS[t][4 * q + 1] = f.y;
        sS[t][4 * q + 2] = f.z; sS[t][4 * q + 3] = f.w;
    }
    __syncthreads();

#pragma unroll
    for (int j = 0; j < 12; ++j) {
        g_tsing[((size_t)j * NSLICE + z) * NPIX + pb + t]
            = make_float2(sS[t][2 * j], sS[t][2 * j + 1]);
    }
}

// ---------------------------------------------------------------------------
// Stage A (radix-2 DIF over z), unchanged from round 12.
// ---------------------------------------------------------------------------
__global__ __launch_bounds__(256, 3)
void stageA_kernel(const float* __restrict__ smap)   // [4,64,64,16,2]
{
    __shared__ float2 T8[8][8];     // w8^(m z0)
    __shared__ float2 T8s[8][8];    // sign(z0) * w8^(m z0)
    __shared__ float2 tws[8];       // sign(z0) * w16^(z0)
    __shared__ float2 sSm[256][17]; // staged smap tile, padded

    const int pixb = blockIdx.x * 256;
    const int t    = threadIdx.x;
    const int pix  = pixb + t;
    const int j    = blockIdx.y;
    const int c    = j & 3;
    const int ne   = j >> 2;               // n*3+e

    if (t < 64) {
        int z0 = t >> 3, m = t & 7;
        float ang = -(2.0f * (float)M_PI / 8.0f) * (float)(m * z0);
        float s, co; sincosf(ang, &s, &co);
        T8[z0][m] = make_float2(co, s);
        float sgn = (z0 & 1) ? -1.0f : 1.0f;
        T8s[z0][m] = make_float2(co * sgn, s * sgn);
    }
    if (t < 8) {
        float ang = -(2.0f * (float)M_PI / 16.0f) * (float)t;
        float s, co; sincosf(ang, &s, &co);
        float sgn = (t & 1) ? -1.0f : 1.0f;
        tws[t] = make_float2(co * sgn, s * sgn);
    }
    {
        const float2* smap2 = (const float2*)(smap) + ((size_t)c * NPIX + pixb) * NSLICE;
        for (int i = t; i < 256 * NSLICE; i += 256)
            sSm[i >> 4][i & 15] = smap2[i];
    }
    __syncthreads();

    const float2* vsrc = g_tsing + (size_t)ne * NSLICE * NPIX + pix;

    float aEr[8], aEi[8], aOr[8], aOi[8];
#pragma unroll
    for (int m = 0; m < 8; ++m) { aEr[m] = 0.f; aEi[m] = 0.f; aOr[m] = 0.f; aOi[m] = 0.f; }

#pragma unroll
    for (int z0 = 0; z0 < 8; ++z0) {
        float2 v0 = vsrc[(size_t)z0 * NPIX];
        float2 v8 = vsrc[(size_t)(z0 + 8) * NPIX];
        float2 s0 = sSm[t][z0];
        float2 s8 = sSm[t][z0 + 8];

        float t0r = v0.x * s0.x - v0.y * s0.y;
        float t0i = v0.x * s0.y + v0.y * s0.x;
        float t8r = v8.x * s8.x - v8.y * s8.y;
        float t8i = v8.x * s8.y + v8.y * s8.x;

        float ar  = t0r + t8r, ai = t0i + t8i;
        float bpr = t0r - t8r, bpi = t0i - t8i;
        float2 tw = tws[z0];
        float br = bpr * tw.x - bpi * tw.y;
        float bi = bpr * tw.y + bpi * tw.x;

#pragma unroll
        for (int m = 0; m < 8; ++m) {
            float2 wE = T8s[z0][m];
            aEr[m] = fmaf(ar, wE.x, aEr[m]);  aEr[m] = fmaf(-ai, wE.y, aEr[m]);
            aEi[m] = fmaf(ar, wE.y, aEi[m]);  aEi[m] = fmaf( ai, wE.x, aEi[m]);
            float2 wO = T8[z0][m];
            aOr[m] = fmaf(br, wO.x, aOr[m]);  aOr[m] = fmaf(-bi, wO.y, aOr[m]);
            aOi[m] = fmaf(br, wO.y, aOi[m]);  aOi[m] = fmaf( bi, wO.x, aOi[m]);
        }
    }

#pragma unroll
    for (int m = 0; m < 8; ++m) {
        g_scf[(((size_t)(2 * m) * NCOIL + c) * 12 + ne) * NPIX + pix]
            = make_float2(aEr[m], aEi[m]);
        g_scf[(((size_t)(2 * m + 1) * NCOIL + c) * 12 + ne) * NPIX + pix]
            = make_float2(aOr[m], aOi[m]);
    }
}

// ---------------------------------------------------------------------------
// Phase tables. grid 32, block 384.
// ---------------------------------------------------------------------------
__global__ __launch_bounds__(384)
void exgen_kernel(const float* __restrict__ ktraj)   // [1,32,96,2]
{
    const int r = blockIdx.x;
    const int p = threadIdx.x % NPT;
    const int g = threadIdx.x / NPT;       // 0..3, 16 steps each
    const float w0 = ktraj[(r * NPT + p) * 2 + 0];
    const float w1 = ktraj[(r * NPT + p) * 2 + 1];

    {
        float s, c; sincosf(w0, &s, &c);                      // step exp(-i*w0)
        float pr, pi; sincosf(w0 * (32.0f - g * 16.0f), &pi, &pr);
#pragma unroll 4
        for (int jj = 0; jj < 16; ++jj) {
            int x = g * 16 + jj;
            g_exp_[((size_t)r * IMG + x) * NPT + p] = make_float2(pr, pi);
            float t = pr;
            pr = fmaf(pr, c, pi * s);
            pi = fmaf(pi, c, -(t * s));
        }
    }
    {
        float s, c; sincosf(w1, &s, &c);
        float pr, pi; sincosf(w1 * (32.0f - g * 16.0f), &pi, &pr);
#pragma unroll 4
        for (int jj = 0; jj < 16; ++jj) {
            int y = g * 16 + jj;
            g_ey_[((size_t)r * IMG + y) * NPT + p] = make_float2(pr, pi);
            float t = pr;
            pr = fmaf(pr, c, pi * s);
            pi = fmaf(pi, c, -(t * s));
        }
    }
}

// ---------------------------------------------------------------------------
// NUFFT via warp-level mma.sync (tf32), k-split across blocks:
//   per (r, ec, kh): partial C[96x128] over y in [32kh, 32kh+32)
//   A = [ey.re | -ey.im] (96 x 64), B rows [x ; 64+x] = [re|im ; im|-re]
// Dedicated C smem buffer + round-12-style coalesced epilogue; partial
// outputs combined with global atomicAdd (out pre-zeroed).
// grid (32 r, 4 ecg, 2 kh), block 256 (8 warps: m2 x n4, 3m x 4n tiles).
// smem ~110.5KB -> 2 blocks/SM; 256 blocks = single wave.
// ---------------------------------------------------------------------------
#define KS2   68                      // float stride (== 4 mod 32)
#define CS    132                     // C row stride
#define A_FL  (96 * KS2)
#define B_FL  (128 * KS2)
#define C_FL  (96 * CS)

__global__ __launch_bounds__(256, 2)
void nufft_mma_kernel(const float* __restrict__ ur_list,   // [1,32,4]
                      const int*   __restrict__ sbin,      // [32]
                      float2* __restrict__ out)            // [96,4,32,3]
{
    extern __shared__ float sh[];
    float*  sA   = sh;                        // [96][KS2]
    float*  sB   = sh + A_FL;                 // [128][KS2]
    float*  sC   = sB + B_FL;                 // [96][CS]
    float2* sPar = (float2*)(sC + C_FL);      // [96][2]

    const int r    = blockIdx.x;
    const int ecg  = blockIdx.y;
    const int kh   = blockIdx.z;              // y-half
    const int tid  = threadIdx.x;
    const int lane = tid & 31;
    const int w    = tid >> 5;      // 0..7
    const int g    = lane >> 2;     // 0..7
    const int tg   = lane & 3;      // 0..3
    const int mg   = w >> 2;        // 0..1  (m-rows 48*mg ..)
    const int ng   = w & 3;         // 0..3  (n-cols 32*ng ..)

    // ---- build A (tf32): A[p][yl] = ey.re[y], A[p][32+yl] = -ey.im[y] ----
    {
        const float2* gey = g_ey_ + ((size_t)r * IMG + 32 * kh) * NPT;
        for (int i = tid; i < 96 * 32; i += 256) {
            int p = i % NPT, yl = i / NPT;
            float2 e = gey[yl * NPT + p];
            sA[p * KS2 + yl]      = tf32r(e.x);
            sA[p * KS2 + 32 + yl] = tf32r(-e.y);
        }
    }

    const int kzr = sbin[r];
    const float u0 = ur_list[r * NSING + 0];
    const float u1 = ur_list[r * NSING + 1];
    const float u2 = ur_list[r * NSING + 2];
    const float u3 = ur_list[r * NSING + 3];

    // per-ec g_scf base (offset to this y-half)
    const float2* bases[3];
#pragma unroll
    for (int it = 0; it < 3; ++it) {
        int ec = ecg * 3 + it;
        bases[it] = g_scf + ((size_t)(kzr * NCOIL + (ec & 3)) * 12 + (ec >> 2)) * NPIX
                  + 32 * kh;
    }

    float mr[8], mi[8];

#define LOAD_MIX(IT)                                                      \
    {                                                                     \
        const float2* base = bases[IT];                                   \
        _Pragma("unroll")                                                 \
        for (int jj = 0; jj < 8; ++jj) {                                  \
            int q  = tid + jj * 256;      /* 0..2047 */                   \
            int x  = q >> 5, yl = q & 31;                                 \
            int ip = x * IMG + yl;                                        \
            float2 s0 = base[ip];                                         \
            float2 s1 = base[ip + 3 * NPIX];                              \
            float2 s2 = base[ip + 6 * NPIX];                              \
            float2 s3 = base[ip + 9 * NPIX];                              \
            mr[jj] = fmaf(u0, s0.x, fmaf(u1, s1.x, fmaf(u2, s2.x, u3 * s3.x))); \
            mi[jj] = fmaf(u0, s0.y, fmaf(u1, s1.y, fmaf(u2, s2.y, u3 * s3.y))); \
        }                                                                 \
    }

#define STORE_B()                                                         \
    {                                                                     \
        _Pragma("unroll")                                                 \
        for (int jj = 0; jj < 8; ++jj) {                                  \
            int q  = tid + jj * 256;                                      \
            int x  = q >> 5, yl = q & 31;                                 \
            float tar = tf32r(mr[jj]), tai = tf32r(mi[jj]);               \
            sB[x * KS2 + yl]             = tar;                           \
            sB[x * KS2 + 32 + yl]        = tai;                           \
            sB[(64 + x) * KS2 + yl]      = tai;                           \
            sB[(64 + x) * KS2 + 32 + yl] = tf32r(-mr[jj]);                \
        }                                                                 \
    }

    // prologue
    LOAD_MIX(0);
    __syncthreads();          // A visible
    STORE_B();
    LOAD_MIX(1);              // prefetch ec1
    __syncthreads();          // B visible

    const float*  Abase = sA + (mg * 48 + g) * KS2 + tg;
    const float2* gex   = g_exp_ + (size_t)r * IMG * NPT;

    for (int it = 0; it < 3; ++it) {
        const int ec = ecg * 3 + it;
        const int e  = ec >> 2;
        const int c  = ec & 3;

        // ---- mma mainloop: K = 64 in 8 k8 steps, 3m x 4n tiles ----
        float d[3][4][4];
#pragma unroll
        for (int mt = 0; mt < 3; ++mt)
#pragma unroll
            for (int nt = 0; nt < 4; ++nt)
#pragma unroll
                for (int q = 0; q < 4; ++q) d[mt][nt][q] = 0.f;

#pragma unroll
        for (int k0 = 0; k0 < 64; k0 += 8) {
            uint32_t a[3][4], b[4][2];
#pragma unroll
            for (int mt = 0; mt < 3; ++mt) {
                const float* ap = Abase + mt * 16 * KS2 + k0;
                a[mt][0] = __float_as_uint(ap[0]);
                a[mt][1] = __float_as_uint(ap[8 * KS2]);
                a[mt][2] = __float_as_uint(ap[4]);
                a[mt][3] = __float_as_uint(ap[8 * KS2 + 4]);
            }
#pragma unroll
            for (int nt = 0; nt < 4; ++nt) {
                const float* bp = sB + (ng * 32 + nt * 8 + g) * KS2 + tg + k0;
                b[nt][0] = __float_as_uint(bp[0]);
                b[nt][1] = __float_as_uint(bp[4]);
            }
#pragma unroll
            for (int mt = 0; mt < 3; ++mt)
#pragma unroll
                for (int nt = 0; nt < 4; ++nt)
                    mma_tf32(d[mt][nt], a[mt], b[nt]);
        }

        __syncthreads();   // B consumed; C free (prev epilogue done)

        // ---- store C + refill B for next ec ----
#pragma unroll
        for (int mt = 0; mt < 3; ++mt) {
#pragma unroll
            for (int nt = 0; nt < 4; ++nt) {
                int p = mg * 48 + mt * 16 + g;
                int n = ng * 32 + nt * 8 + 2 * tg;
                sC[p * CS + n]           = d[mt][nt][0];
                sC[p * CS + n + 1]       = d[mt][nt][1];
                sC[(p + 8) * CS + n]     = d[mt][nt][2];
                sC[(p + 8) * CS + n + 1] = d[mt][nt][3];
            }
        }
        if (it < 2) STORE_B();
        if (it < 1) LOAD_MIX(2);
        __syncthreads();   // C + new B visible

        // ---- ex contraction (round-12 style): tid<192, h = x-half ----
        if (tid < 192) {
            int p = tid % 96, h = tid / 96;          // h 0..1
            float orr = 0.f, oii = 0.f;
            const float* rowp = sC + p * CS;
#pragma unroll 8
            for (int x = 32 * h; x < 32 * h + 32; ++x) {
                float tr = rowp[x];
                float ti = rowp[64 + x];
                float2 ex = gex[x * NPT + p];
                orr = fmaf(tr,  ex.x, orr);
                orr = fmaf(-ti, ex.y, orr);
                oii = fmaf(tr,  ex.y, oii);
                oii = fmaf(ti,  ex.x, oii);
            }
            sPar[p * 2 + h] = make_float2(orr, oii);
        }
        __syncthreads();

        if (tid < NPT) {
            float2 v0 = sPar[tid * 2 + 0];
            float2 v1 = sPar[tid * 2 + 1];
            float* dst = (float*)&out[((tid * NCOIL + c) * NRO + r) * NECHO + e];
            atomicAdd(dst,     v0.x + v1.x);
            atomicAdd(dst + 1, v0.y + v1.y);
        }
        // no barrier needed here: next phase (mma) touches only sA/sB,
        // and the next C-store is gated by the post-mma barrier.
    }
#undef LOAD_MIX
#undef STORE_B
}

// ---------------------------------------------------------------------------
extern "C" void kernel_launch(void* const* d_in, const int* in_sizes, int n_in,
                              void* d_out, int out_size)
{
    const float* singulars = (const float*)d_in[0];
    const float* smap      = (const float*)d_in[1];
    const float* ktraj     = (const float*)d_in[2];
    const float* ur_list   = (const float*)d_in[3];
    const int*   sbin      = (const int*)d_in[4];
    // d_in[5] = dc (unused by the forward reference)

    float2* out = (float2*)d_out;

    const int smemNufft = (A_FL + B_FL + C_FL) * (int)sizeof(float)
                        + 96 * 2 * (int)sizeof(float2);    // ~110.5KB
    cudaFuncSetAttribute(nufft_mma_kernel,
                         cudaFuncAttributeMaxDynamicSharedMemorySize, smemNufft);

    cudaMemsetAsync(d_out, 0, (size_t)out_size * sizeof(float));
    transpose_kernel<<<dim3(16, 16), 256>>>(singulars);
    exgen_kernel<<<NRO, 384>>>(ktraj);
    stageA_kernel<<<dim3(16, 48), 256>>>(smap);
    nufft_mma_kernel<<<dim3(NRO, 4, 2), 256, smemNufft>>>(ur_list, sbin, out);
}

// round 15
// speedup vs baseline: 1.3529x; 1.1293x over previous
#include <cuda_runtime.h>
#include <math.h>
#include <stdint.h>

#define IMG    64
#define NSLICE 16
#define NCOIL  4
#define NSING  4
#define NECHO  3
#define NRO    32
#define NPT    96
#define NEC    (NECHO * NCOIL)   // 12
#define NPIX   (IMG * IMG)       // 4096

// scf[kz][c][ne=n*3+e][pix]  (25 MB)   pixel index = X*64+Y (X major)
__device__ float2 g_scf[NSLICE * NCOIL * (NSING * NECHO) * NPIX];
// transposed singulars: tsing[ne][z][pix]  (6.3 MB)
__device__ float2 g_tsing[(NSING * NECHO) * NSLICE * NPIX];
// phase tables
__device__ float2 g_exp_[NRO * IMG * NPT];   // ex[r][x][p] = exp(-i*w0*(x-32))
__device__ float2 g_ey_[NRO * IMG * NPT];    // ey[r][y][p] = exp(-i*w1*(y-32))

// ---------------------------------------------------------------------------
// helpers
// ---------------------------------------------------------------------------
__device__ __forceinline__ float tf32r(float f) {
    uint32_t u;
    asm("cvt.rn.tf32.f32 %0, %1;" : "=r"(u) : "f"(f));
    return __uint_as_float(u);
}
__device__ __forceinline__ void mma_tf32(float* d, const uint32_t* a, const uint32_t* b) {
    asm volatile(
        "mma.sync.aligned.m16n8k8.row.col.f32.tf32.tf32.f32 "
        "{%0,%1,%2,%3}, {%4,%5,%6,%7}, {%8,%9}, {%0,%1,%2,%3};"
        : "+f"(d[0]), "+f"(d[1]), "+f"(d[2]), "+f"(d[3])
        : "r"(a[0]), "r"(a[1]), "r"(a[2]), "r"(a[3]), "r"(b[0]), "r"(b[1]));
}

// packed-fragment A write: A[96 rows][128 k] -> [6 mt][16 kstep][32 lane] float4
// lane = g*4+tg; float4 = (A[R+g][k0+tg], A[R+8+g][k0+tg],
//                          A[R+g][k0+4+tg], A[R+8+g][k0+4+tg])
__device__ __forceinline__ void awrite(float* dst, int p, int k, float v) {
    int mt = p >> 4, g = p & 7, hi = (p >> 3) & 1;
    int kstep = k >> 3, tg = k & 3, kh = (k >> 2) & 1;
    dst[((((mt * 16 + kstep) * 32) + g * 4 + tg) << 2) + kh * 2 + hi] = v;
}
// packed-fragment B write: B[128 rows][128 k] -> [16 ntile][16 kstep][34 pad] float2
// lane = g*4+tg; float2 = (B[N8+g][k0+tg], B[N8+g][k0+4+tg])
__device__ __forceinline__ void bwrite(float* dst, int row, int k, float v) {
    int ntile = row >> 3, g = row & 7;
    int kstep = k >> 3, tg = k & 3, kh = (k >> 2) & 1;
    dst[((((ntile * 16 + kstep) * 34) + g * 4 + tg) << 1) + kh] = v;
}

// ---------------------------------------------------------------------------
// Transpose: singulars [pix][z][ne]{2} -> g_tsing [ne][z][pix]{2}
// ---------------------------------------------------------------------------
__global__ __launch_bounds__(256)
void transpose_kernel(const float* __restrict__ singulars)   // [64,64,16,4,3,2]
{
    __shared__ float sS[256][25];   // 24 floats + pad
    const int z  = blockIdx.y;
    const int pb = blockIdx.x * 256;
    const int t  = threadIdx.x;

    const float4* src = (const float4*)(singulars + (size_t)(pb + t) * 384 + z * 24);
#pragma unroll
    for (int q = 0; q < 6; ++q) {
        float4 f = src[q];
        sS[t][4 * q + 0] = f.x; sS[t][4 * q + 1] = f.y;
        sS[t][4 * q + 2] = f.z; sS[t][4 * q + 3] = f.w;
    }
    __syncthreads();

#pragma unroll
    for (int j = 0; j < 12; ++j) {
        g_tsing[((size_t)j * NSLICE + z) * NPIX + pb + t]
            = make_float2(sS[t][2 * j], sS[t][2 * j + 1]);
    }
}

// ---------------------------------------------------------------------------
// Stage A (radix-2 DIF over z), unchanged from round 12.
// ---------------------------------------------------------------------------
__global__ __launch_bounds__(256, 3)
void stageA_kernel(const float* __restrict__ smap)   // [4,64,64,16,2]
{
    __shared__ float2 T8[8][8];     // w8^(m z0)
    __shared__ float2 T8s[8][8];    // sign(z0) * w8^(m z0)
    __shared__ float2 tws[8];       // sign(z0) * w16^(z0)
    __shared__ float2 sSm[256][17]; // staged smap tile, padded

    const int pixb = blockIdx.x * 256;
    const int t    = threadIdx.x;
    const int pix  = pixb + t;
    const int j    = blockIdx.y;
    const int c    = j & 3;
    const int ne   = j >> 2;               // n*3+e

    if (t < 64) {
        int z0 = t >> 3, m = t & 7;
        float ang = -(2.0f * (float)M_PI / 8.0f) * (float)(m * z0);
        float s, co; sincosf(ang, &s, &co);
        T8[z0][m] = make_float2(co, s);
        float sgn = (z0 & 1) ? -1.0f : 1.0f;
        T8s[z0][m] = make_float2(co * sgn, s * sgn);
    }
    if (t < 8) {
        float ang = -(2.0f * (float)M_PI / 16.0f) * (float)t;
        float s, co; sincosf(ang, &s, &co);
        float sgn = (t & 1) ? -1.0f : 1.0f;
        tws[t] = make_float2(co * sgn, s * sgn);
    }
    {
        const float2* smap2 = (const float2*)(smap) + ((size_t)c * NPIX + pixb) * NSLICE;
        for (int i = t; i < 256 * NSLICE; i += 256)
            sSm[i >> 4][i & 15] = smap2[i];
    }
    __syncthreads();

    const float2* vsrc = g_tsing + (size_t)ne * NSLICE * NPIX + pix;

    float aEr[8], aEi[8], aOr[8], aOi[8];
#pragma unroll
    for (int m = 0; m < 8; ++m) { aEr[m] = 0.f; aEi[m] = 0.f; aOr[m] = 0.f; aOi[m] = 0.f; }

#pragma unroll
    for (int z0 = 0; z0 < 8; ++z0) {
        float2 v0 = vsrc[(size_t)z0 * NPIX];
        float2 v8 = vsrc[(size_t)(z0 + 8) * NPIX];
        float2 s0 = sSm[t][z0];
        float2 s8 = sSm[t][z0 + 8];

        float t0r = v0.x * s0.x - v0.y * s0.y;
        float t0i = v0.x * s0.y + v0.y * s0.x;
        float t8r = v8.x * s8.x - v8.y * s8.y;
        float t8i = v8.x * s8.y + v8.y * s8.x;

        float ar  = t0r + t8r, ai = t0i + t8i;
        float bpr = t0r - t8r, bpi = t0i - t8i;
        float2 tw = tws[z0];
        float br = bpr * tw.x - bpi * tw.y;
        float bi = bpr * tw.y + bpi * tw.x;

#pragma unroll
        for (int m = 0; m < 8; ++m) {
            float2 wE = T8s[z0][m];
            aEr[m] = fmaf(ar, wE.x, aEr[m]);  aEr[m] = fmaf(-ai, wE.y, aEr[m]);
            aEi[m] = fmaf(ar, wE.y, aEi[m]);  aEi[m] = fmaf( ai, wE.x, aEi[m]);
            float2 wO = T8[z0][m];
            aOr[m] = fmaf(br, wO.x, aOr[m]);  aOr[m] = fmaf(-bi, wO.y, aOr[m]);
            aOi[m] = fmaf(br, wO.y, aOi[m]);  aOi[m] = fmaf( bi, wO.x, aOi[m]);
        }
    }

#pragma unroll
    for (int m = 0; m < 8; ++m) {
        g_scf[(((size_t)(2 * m) * NCOIL + c) * 12 + ne) * NPIX + pix]
            = make_float2(aEr[m], aEi[m]);
        g_scf[(((size_t)(2 * m + 1) * NCOIL + c) * 12 + ne) * NPIX + pix]
            = make_float2(aOr[m], aOi[m]);
    }
}

// ---------------------------------------------------------------------------
// Phase tables. grid 32, block 384.
// ---------------------------------------------------------------------------
__global__ __launch_bounds__(384)
void exgen_kernel(const float* __restrict__ ktraj)   // [1,32,96,2]
{
    const int r = blockIdx.x;
    const int p = threadIdx.x % NPT;
    const int g = threadIdx.x / NPT;       // 0..3, 16 steps each
    const float w0 = ktraj[(r * NPT + p) * 2 + 0];
    const float w1 = ktraj[(r * NPT + p) * 2 + 1];

    {
        float s, c; sincosf(w0, &s, &c);                      // step exp(-i*w0)
        float pr, pi; sincosf(w0 * (32.0f - g * 16.0f), &pi, &pr);
#pragma unroll 4
        for (int jj = 0; jj < 16; ++jj) {
            int x = g * 16 + jj;
            g_exp_[((size_t)r * IMG + x) * NPT + p] = make_float2(pr, pi);
            float t = pr;
            pr = fmaf(pr, c, pi * s);
            pi = fmaf(pi, c, -(t * s));
        }
    }
    {
        float s, c; sincosf(w1, &s, &c);
        float pr, pi; sincosf(w1 * (32.0f - g * 16.0f), &pi, &pr);
#pragma unroll 4
        for (int jj = 0; jj < 16; ++jj) {
            int y = g * 16 + jj;
            g_ey_[((size_t)r * IMG + y) * NPT + p] = make_float2(pr, pi);
            float t = pr;
            pr = fmaf(pr, c, pi * s);
            pi = fmaf(pi, c, -(t * s));
        }
    }
}

// ---------------------------------------------------------------------------
// NUFFT via warp-level mma.sync (tf32), round-12 structure with
// fragment-packed smem layouts:
//   A: [6 mt][16 kstep][32 lane] float4 -> 1 LDS.128 per (mt,kstep)
//   B: [16 ntile][16 kstep][34] float2  -> 1 LDS.64 per (nt,kstep)
// Double-buffered B with register prefetch; C overlays the retiring B buffer.
// grid (32 r, 4 ecg), block 512 (16 warps: m2 x n8, 3m x 2n tiles).
// ---------------------------------------------------------------------------
#define A_FL   (6 * 16 * 32 * 4)      // 12288 floats (48KB)
#define B_FL   (16 * 16 * 34 * 2)     // 17408 floats (68KB)
#define CS     132                    // C row stride (overlay, fits in B_FL)

__global__ __launch_bounds__(512, 1)
void nufft_mma_kernel(const float* __restrict__ ur_list,   // [1,32,4]
                      const int*   __restrict__ sbin,      // [32]
                      float2* __restrict__ out)            // [96,4,32,3]
{
    extern __shared__ float sh[];
    float*  sA   = sh;                        // packed A
    float*  sB0  = sh + A_FL;                 // packed B buf 0
    float*  sB1  = sB0 + B_FL;                // packed B buf 1
    float2* sPar = (float2*)(sB1 + B_FL);     // [96][4]

    const int r    = blockIdx.x;
    const int ecg  = blockIdx.y;
    const int tid  = threadIdx.x;
    const int lane = tid & 31;
    const int w    = tid >> 5;      // 0..15
    const int mg   = w >> 3;        // 0..1  (m-rows 48*mg ..)
    const int ng   = w & 7;         // 0..7  (n-cols 16*ng ..)

    // ---- build A (tf32, packed): A[p][y] = ey.re, A[p][64+y] = -ey.im ----
    {
        const float2* gey = g_ey_ + (size_t)r * IMG * NPT;
        for (int i = tid; i < IMG * NPT; i += 512) {
            int y = i / NPT, p = i % NPT;
            float2 e = gey[i];
            awrite(sA, p, y,      tf32r(e.x));
            awrite(sA, p, 64 + y, tf32r(-e.y));
        }
    }

    const int kzr = sbin[r];
    const float u0 = ur_list[r * NSING + 0];
    const float u1 = ur_list[r * NSING + 1];
    const float u2 = ur_list[r * NSING + 2];
    const float u3 = ur_list[r * NSING + 3];

    const float2* bases[3];
#pragma unroll
    for (int it = 0; it < 3; ++it) {
        int ec = ecg * 3 + it;
        bases[it] = g_scf + ((size_t)(kzr * NCOIL + (ec & 3)) * 12 + (ec >> 2)) * NPIX;
    }

    float mr[8], mi[8];   // prefetched+mixed image values for next B

#define LOAD_MIX(IT)                                                      \
    {                                                                     \
        const float2* base = bases[IT];                                   \
        _Pragma("unroll")                                                 \
        for (int jj = 0; jj < 8; ++jj) {                                  \
            int i = tid + jj * 512;                                       \
            float2 s0 = base[i];                                          \
            float2 s1 = base[i + 3 * NPIX];                               \
            float2 s2 = base[i + 6 * NPIX];                               \
            float2 s3 = base[i + 9 * NPIX];                               \
            mr[jj] = fmaf(u0, s0.x, fmaf(u1, s1.x, fmaf(u2, s2.x, u3 * s3.x))); \
            mi[jj] = fmaf(u0, s0.y, fmaf(u1, s1.y, fmaf(u2, s2.y, u3 * s3.y))); \
        }                                                                 \
    }

    // B rows: [x] = [re | im], [64+x] = [im | -re]  (k = y, 64+y), packed
#define STORE_B(BUF)                                                      \
    {                                                                     \
        float* dst = (BUF);                                               \
        _Pragma("unroll")                                                 \
        for (int jj = 0; jj < 8; ++jj) {                                  \
            int i = tid + jj * 512;                                       \
            int x = i >> 6, y = i & 63;                                   \
            float tar = tf32r(mr[jj]), tai = tf32r(mi[jj]);               \
            bwrite(dst, x,      y,      tar);                             \
            bwrite(dst, x,      64 + y, tai);                             \
            bwrite(dst, 64 + x, y,      tai);                             \
            bwrite(dst, 64 + x, 64 + y, tf32r(-mr[jj]));                  \
        }                                                                 \
    }

    // prologue
    LOAD_MIX(0);
    __syncthreads();          // A visible
    STORE_B(sB0);
    LOAD_MIX(1);              // prefetch ec1 (LDGs in flight through mma(0))
    __syncthreads();          // B0 visible

    const float4* sA4  = (const float4*)sA;
    const float2* gex  = g_exp_ + (size_t)r * IMG * NPT;

    for (int it = 0; it < 3; ++it) {
        const int ec = ecg * 3 + it;
        const int e  = ec >> 2;
        const int c  = ec & 3;
        float* bufc = (it & 1) ? sB1 : sB0;
        float* bufn = (it & 1) ? sB0 : sB1;
        const float2* sB2 = (const float2*)bufc;

        // ---- mma mainloop: K = 128 in 16 k8 steps ----
        float d[3][2][4];
#pragma unroll
        for (int mt = 0; mt < 3; ++mt)
#pragma unroll
            for (int nt = 0; nt < 2; ++nt)
#pragma unroll
                for (int q = 0; q < 4; ++q) d[mt][nt][q] = 0.f;

#pragma unroll
        for (int kstep = 0; kstep < 16; ++kstep) {
            uint32_t a[3][4], b[2][2];
#pragma unroll
            for (int mt = 0; mt < 3; ++mt) {
                float4 av = sA4[(((mg * 3 + mt) * 16 + kstep) << 5) + lane];
                a[mt][0] = __float_as_uint(av.x);
                a[mt][1] = __float_as_uint(av.y);
                a[mt][2] = __float_as_uint(av.z);
                a[mt][3] = __float_as_uint(av.w);
            }
#pragma unroll
            for (int nt = 0; nt < 2; ++nt) {
                float2 bv = sB2[((ng * 2 + nt) * 16 + kstep) * 34 + lane];
                b[nt][0] = __float_as_uint(bv.x);
                b[nt][1] = __float_as_uint(bv.y);
            }
#pragma unroll
            for (int mt = 0; mt < 3; ++mt)
#pragma unroll
                for (int nt = 0; nt < 2; ++nt)
                    mma_tf32(d[mt][nt], a[mt], b[nt]);
        }

        // write next B while mma results settle (prefetched regs)
        if (it < 2) STORE_B(bufn);
        if (it < 1) LOAD_MIX(2);     // prefetch last ec

        __syncthreads();   // mma reads of bufc done

        // ---- store C (t1) into bufc overlay: t1[p][ncol], rows 0..95 ----
        {
            const int g  = lane >> 2;
            const int tg = lane & 3;
#pragma unroll
            for (int mt = 0; mt < 3; ++mt) {
#pragma unroll
                for (int nt = 0; nt < 2; ++nt) {
                    int p = mg * 48 + mt * 16 + g;
                    int n = ng * 16 + nt * 8 + 2 * tg;
                    bufc[p * CS + n]           = d[mt][nt][0];
                    bufc[p * CS + n + 1]       = d[mt][nt][1];
                    bufc[(p + 8) * CS + n]     = d[mt][nt][2];
                    bufc[(p + 8) * CS + n + 1] = d[mt][nt][3];
                }
            }
        }
        __syncthreads();

        // ---- ex contraction: thread (p, h) handles x in [16h, 16h+16) ----
        if (tid < 384) {
            int p = tid % 96, h = tid / 96;          // h 0..3
            float orr = 0.f, oii = 0.f;
            const float* rowp = bufc + p * CS;
#pragma unroll 8
            for (int x = 16 * h; x < 16 * h + 16; ++x) {
                float tr = rowp[x];
                float ti = rowp[64 + x];
                float2 ex = gex[x * NPT + p];
                orr = fmaf(tr,  ex.x, orr);
                orr = fmaf(-ti, ex.y, orr);
                oii = fmaf(tr,  ex.y, oii);
                oii = fmaf(ti,  ex.x, oii);
            }
            sPar[p * 4 + h] = make_float2(orr, oii);
        }
        __syncthreads();

        if (tid < NPT) {
            float2 v0 = sPar[tid * 4 + 0];
            float2 v1 = sPar[tid * 4 + 1];
            float2 v2 = sPar[tid * 4 + 2];
            float2 v3 = sPar[tid * 4 + 3];
            out[((tid * NCOIL + c) * NRO + r) * NECHO + e]
                = make_float2(v0.x + v1.x + v2.x + v3.x,
                              v0.y + v1.y + v2.y + v3.y);
        }
    }
#undef LOAD_MIX
#undef STORE_B
}

// ---------------------------------------------------------------------------
extern "C" void kernel_launch(void* const* d_in, const int* in_sizes, int n_in,
                              void* d_out, int out_size)
{
    const float* singulars = (const float*)d_in[0];
    const float* smap      = (const float*)d_in[1];
    const float* ktraj     = (const float*)d_in[2];
    const float* ur_list   = (const float*)d_in[3];
    const int*   sbin      = (const int*)d_in[4];
    // d_in[5] = dc (unused by the forward reference)

    float2* out = (float2*)d_out;

    const int smemNufft = (A_FL + 2 * B_FL) * (int)sizeof(float)
                        + 96 * 4 * (int)sizeof(float2);    // ~187KB
    cudaFuncSetAttribute(nufft_mma_kernel,
                         cudaFuncAttributeMaxDynamicSharedMemorySize, smemNufft);

    transpose_kernel<<<dim3(16, 16), 256>>>(singulars);
    exgen_kernel<<<NRO, 384>>>(ktraj);
    stageA_kernel<<<dim3(16, 48), 256>>>(smap);
    nufft_mma_kernel<<<dim3(NRO, 4), 512, smemNufft>>>(ur_list, sbin, out);
}